// round 13
// baseline (speedup 1.0000x reference)
#include <cuda_runtime.h>
#include <cuda_fp16.h>
#include <math.h>
#include <stdint.h>

#define BB 2
#define SS 256
#define DD 128
#define LL 2
#define NN 512
#define HH 8
#define DHH 16
#define VV 50257
#define BS 512
#define TWO_D 256
#define PHI_F 1.6180339887498949f

// ---------------- scratch (device globals; no allocations allowed) ----------------
__device__ float g_states[BS * DD];
__device__ float g_x[BS * DD];
__device__ float g_xT[DD * BS];
__device__ float g_q[BS * HH * 32];
__device__ float g_kT[BB * HH * 32 * SS];
__device__ float g_csumT[NN * BS];
__device__ float g_ssumT[NN * BS];
__device__ float g_context[BS * DD];
__device__ float g_respart[16 * BS * DD];
// fp16 operands for the tensor-core logits GEMM
__device__ __align__(16) __half g_xh[BS * DD];
__device__ __align__(16) __half g_Wh[VV * DD];

// Accurate sincos regardless of fast-math flags: Cody-Waite reduce to
// [-pi,pi], then fast-path __sincosf (error ~2^-21 there).
__device__ __forceinline__ void my_sincos(float th, float* sp, float* cp) {
    float k = rintf(th * 0.15915494309189535f);
    float r = fmaf(k, -6.28125f, th);
    r = fmaf(k, -1.9353071795864769e-3f, r);
    __sincosf(r, sp, cp);
}

// ---------------- K0: Wo fp32 -> fp16 (once per call; overlapped on stream 2) ------
__global__ void cvt_w_kernel(const float* __restrict__ Wo) {
    int i = blockIdx.x * 256 + threadIdx.x;   // over VV*DD/4
    if (i >= (VV * DD) / 4) return;
    float4 v = reinterpret_cast<const float4*>(Wo)[i];
    __half2 p0 = __floats2half2_rn(v.x, v.y);
    __half2 p1 = __floats2half2_rn(v.z, v.w);
    uint2 u = make_uint2(*reinterpret_cast<unsigned*>(&p0), *reinterpret_cast<unsigned*>(&p1));
    reinterpret_cast<uint2*>(g_Wh)[i] = u;
}

// ---------------- K1: embedding + sequential scan, chunked register prefetch -------
#define CH 16
__global__ void scan_kernel(const int* __restrict__ tokens, const float* __restrict__ emb) {
    int b = blockIdx.x, d = threadIdx.x;
    const int* tk = tokens + b * SS;
    float w_r[CH], be_r[CH];

#pragma unroll
    for (int i = 0; i < CH; ++i) {
        int tok = __ldg(&tk[i]);
        w_r[i]  = __ldg(&emb[tok * TWO_D + d]);
        be_r[i] = __ldg(&emb[tok * TWO_D + DD + d]);
    }

    float s = 0.f;
    for (int c = 0; c < SS / CH; ++c) {
        float inv_c[CH], base_c[CH];
#pragma unroll
        for (int i = 0; i < CH; ++i) {
            inv_c[i]  = __fdividef(1.f, 1.f + fabsf(w_r[i]));
            base_c[i] = fmaf((float)(c * CH + i), PHI_F, be_r[i]);
        }
        if (c + 1 < SS / CH) {
#pragma unroll
            for (int i = 0; i < CH; ++i) {
                int tok = __ldg(&tk[(c + 1) * CH + i]);
                w_r[i]  = __ldg(&emb[tok * TWO_D + d]);
                be_r[i] = __ldg(&emb[tok * TWO_D + DD + d]);
            }
        }
#pragma unroll
        for (int i = 0; i < CH; ++i) {
            float th = fmaf(s, inv_c[i], base_c[i]);
            float sv, cv; my_sincos(th, &sv, &cv);
            s = cv + sv;
            int bs = b * SS + c * CH + i;
            g_states[bs * DD + d] = s;
            g_x[bs * DD + d] = s;
            g_xT[d * BS + bs] = s;
        }
    }
}

// ---------------- K2: build q and transposed k ----------------
__global__ void qk_kernel(const float* __restrict__ wq, const float* __restrict__ bq,
                          const float* __restrict__ wk, const float* __restrict__ bk, int l) {
    int bs = blockIdx.x, d = threadIdx.x;
    int h = d >> 4, dh = d & 15;
    int t = bs & (SS - 1);
    float tphi = (float)t * PHI_F;
    int wi = (l * HH + h) * DHH + dh;

    float xv = g_x[bs * DD + d];
    float iq = __fdividef(1.f, 1.f + fabsf(wq[wi]));
    float thq = fmaf(xv, iq, bq[wi] + tphi);
    float sq, cq; my_sincos(thq, &sq, &cq);
    int qb = bs * (HH * 32) + h * 32;
    g_q[qb + dh] = cq;
    g_q[qb + 16 + dh] = sq;

    float sv = g_states[bs * DD + d];
    float ik = __fdividef(1.f, 1.f + fabsf(wk[wi]));
    float thk = fmaf(sv, ik, bk[wi]);
    float sk, ck; my_sincos(thk, &sk, &ck);
    int b = bs >> 8, si = bs & 255;
    int kb = (b * HH + h) * 32;
    g_kT[(kb + dh) * SS + si] = ck;
    g_kT[(kb + 16 + dh) * SS + si] = sk;
}

// ---------------- K3: scores + softmax + head-sum + context, one query/block -------
// (R12 measured win: 512 blocks, occ 43%, 22.6us)
__global__ __launch_bounds__(256) void scores_kernel() {
    int q = blockIdx.x, b = blockIdx.y;
    int tid = threadIdx.x;
    int h = tid >> 5, lane = tid & 31;
    __shared__ float q_sh[HH * 32];
    __shared__ float wts_sh[HH][SS];
    __shared__ float wsum_sh[SS];
    __shared__ float red_sh[DD];

    q_sh[tid] = g_q[(b * SS + q) * (HH * 32) + tid];
    __syncthreads();

    const float* kbase = g_kT + (b * HH + h) * 32 * SS;
    float acc[8];
#pragma unroll
    for (int j = 0; j < 8; ++j) acc[j] = 0.f;

#pragma unroll 8
    for (int dd = 0; dd < 32; ++dd) {
        const float4* row = reinterpret_cast<const float4*>(kbase + dd * SS);
        float4 v0 = row[lane];
        float4 v1 = row[lane + 32];
        float qv = q_sh[h * 32 + dd];
        acc[0] = fmaf(qv, v0.x, acc[0]); acc[1] = fmaf(qv, v0.y, acc[1]);
        acc[2] = fmaf(qv, v0.z, acc[2]); acc[3] = fmaf(qv, v0.w, acc[3]);
        acc[4] = fmaf(qv, v1.x, acc[4]); acc[5] = fmaf(qv, v1.y, acc[5]);
        acc[6] = fmaf(qv, v1.z, acc[6]); acc[7] = fmaf(qv, v1.w, acc[7]);
    }

    const float iscale = 0.17677669529663687f;  // 1/sqrt(32)
    int k0 = 4 * lane;
    float m = -1e30f;
#pragma unroll
    for (int j = 0; j < 8; ++j) {
        acc[j] *= iscale;
        int ki = (j < 4) ? (k0 + j) : (128 + k0 + j - 4);
        if (ki <= q && acc[j] > m) m = acc[j];
    }
#pragma unroll
    for (int o = 16; o; o >>= 1) m = fmaxf(m, __shfl_xor_sync(0xffffffffu, m, o));
    float e[8]; float sum = 0.f;
#pragma unroll
    for (int j = 0; j < 8; ++j) {
        int ki = (j < 4) ? (k0 + j) : (128 + k0 + j - 4);
        e[j] = (ki <= q) ? __expf(acc[j] - m) : 0.f;
        sum += e[j];
    }
#pragma unroll
    for (int o = 16; o; o >>= 1) sum += __shfl_xor_sync(0xffffffffu, sum, o);
    float inv = __fdividef(1.f, sum);
    float4 w0 = make_float4(e[0] * inv, e[1] * inv, e[2] * inv, e[3] * inv);
    float4 w1 = make_float4(e[4] * inv, e[5] * inv, e[6] * inv, e[7] * inv);
    reinterpret_cast<float4*>(&wts_sh[h][0])[lane] = w0;
    reinterpret_cast<float4*>(&wts_sh[h][0])[lane + 32] = w1;
    __syncthreads();

    float ws = 0.f;
#pragma unroll
    for (int hh = 0; hh < HH; ++hh) ws += wts_sh[hh][tid];
    wsum_sh[tid] = ws;
    __syncthreads();

    int d = tid & 127, half = tid >> 7;
    float cacc = 0.f;
    const float* st = g_states + b * SS * DD + d;
    int kbeg = half << 7;
#pragma unroll 8
    for (int k = kbeg; k < kbeg + 128; ++k)
        cacc = fmaf(wsum_sh[k], st[k * DD], cacc);
    if (half == 1) red_sh[d] = cacc;
    __syncthreads();
    if (half == 0) g_context[(b * SS + q) * DD + d] = cacc + red_sh[d];
}

// ---------------- K6: FFN random-feature sums (R11 interleaved form — reverted) ----
__global__ __launch_bounds__(256) void ffn_kernel(const float* __restrict__ Wf,
                                                  const float* __restrict__ Bf, int l) {
    int n0 = blockIdx.x * 2, tid = threadIdx.x;
    int bs = blockIdx.y * 256 + tid;
    __shared__ float inv_sh[2][DD], c_sh[2][DD];
    {
        int np = tid >> 7, d = tid & 127;
        inv_sh[np][d] = __fdividef(1.f, 1.f + fabsf(Wf[(l * NN + n0 + np) * DD + d]));
        c_sh[np][d] = Bf[(l * NN + n0 + np) * DD + d];
    }
    __syncthreads();

    float ac[2] = {0.f, 0.f}, as2[2] = {0.f, 0.f};
#pragma unroll 4
    for (int dd = 0; dd < DD; ++dd) {
        float xv = g_xT[dd * BS + bs];
        float su, cu;
        __sincosf(fmaf(xv, inv_sh[0][dd], c_sh[0][dd]), &su, &cu);
        ac[0] += cu; as2[0] += su;
        __sincosf(fmaf(xv, inv_sh[1][dd], c_sh[1][dd]), &su, &cu);
        ac[1] += cu; as2[1] += su;
    }
    float st0, ct0;
    my_sincos((float)(bs & (SS - 1)), &st0, &ct0);
#pragma unroll
    for (int np = 0; np < 2; ++np) {
        int n = n0 + np;
        g_csumT[n * BS + bs] = ct0 * ac[np] - st0 * as2[np];
        g_ssumT[n * BS + bs] = st0 * ac[np] + ct0 * as2[np];
    }
}

// ---------------- K7a: res partial GEMM (k-split x16) ----------------
__global__ __launch_bounds__(256) void proj_kernel(const float* __restrict__ Pr,
                                                   const float* __restrict__ Pi, int l) {
    int m0 = blockIdx.x * 64;
    int p = blockIdx.y;
    int k0 = p * 32;
    int tid = threadIdx.x;
    int tx = tid & 15, ty = tid >> 4;
    __shared__ float Ac[16][64], As2[16][64], Br[16][128], Bi[16][128];
    float acc[4][8];
#pragma unroll
    for (int i = 0; i < 4; ++i)
#pragma unroll
        for (int j = 0; j < 8; ++j) acc[i][j] = 0.f;

    for (int kc = 0; kc < 2; ++kc) {
        int kb = k0 + kc * 16;
        {
            int r = tid >> 4, c4 = tid & 15;
            float4 v = *reinterpret_cast<const float4*>(g_csumT + (kb + r) * BS + m0 + c4 * 4);
            Ac[r][c4 * 4 + 0] = v.x; Ac[r][c4 * 4 + 1] = v.y;
            Ac[r][c4 * 4 + 2] = v.z; Ac[r][c4 * 4 + 3] = v.w;
            float4 v2 = *reinterpret_cast<const float4*>(g_ssumT + (kb + r) * BS + m0 + c4 * 4);
            As2[r][c4 * 4 + 0] = v2.x; As2[r][c4 * 4 + 1] = v2.y;
            As2[r][c4 * 4 + 2] = v2.z; As2[r][c4 * 4 + 3] = v2.w;
        }
#pragma unroll
        for (int i = 0; i < 2; ++i) {
            int idx = tid * 2 + i;
            int dcol = idx >> 2, k4 = idx & 3;
            float4 v = *reinterpret_cast<const float4*>(Pr + (l * DD + dcol) * NN + kb + k4 * 4);
            Br[k4 * 4 + 0][dcol] = v.x; Br[k4 * 4 + 1][dcol] = v.y;
            Br[k4 * 4 + 2][dcol] = v.z; Br[k4 * 4 + 3][dcol] = v.w;
            float4 v2 = *reinterpret_cast<const float4*>(Pi + (l * DD + dcol) * NN + kb + k4 * 4);
            Bi[k4 * 4 + 0][dcol] = v2.x; Bi[k4 * 4 + 1][dcol] = v2.y;
            Bi[k4 * 4 + 2][dcol] = v2.z; Bi[k4 * 4 + 3][dcol] = v2.w;
        }
        __syncthreads();
#pragma unroll
        for (int kk = 0; kk < 16; ++kk) {
            float a_c[4], a_s[4], b_r[8], b_i[8];
#pragma unroll
            for (int i = 0; i < 4; ++i) { a_c[i] = Ac[kk][ty * 4 + i]; a_s[i] = As2[kk][ty * 4 + i]; }
#pragma unroll
            for (int j = 0; j < 8; ++j) { b_r[j] = Br[kk][tx * 8 + j]; b_i[j] = Bi[kk][tx * 8 + j]; }
#pragma unroll
            for (int i = 0; i < 4; ++i)
#pragma unroll
                for (int j = 0; j < 8; ++j)
                    acc[i][j] = fmaf(a_s[i], b_i[j], fmaf(a_c[i], b_r[j], acc[i][j]));
        }
        __syncthreads();
    }
#pragma unroll
    for (int i = 0; i < 4; ++i)
#pragma unroll
        for (int j = 0; j < 8; ++j)
            g_respart[(p * BS + m0 + ty * 4 + i) * DD + tx * 8 + j] = acc[i][j];
}

// ---------------- K7b: attn_out + silu(res) + x update (+fp16 on last layer) --------
__global__ void update_kernel(const float* __restrict__ w_out, const float* __restrict__ b_out,
                              const float* __restrict__ out_scale, const float* __restrict__ attn_scale,
                              const float* __restrict__ res_scale, int l, int last) {
    int bs = blockIdx.x, d = threadIdx.x;
    float ctx = g_context[bs * DD + d];
    float inv = __fdividef(1.f, 1.f + fabsf(w_out[l * DD + d]));
    float tphi = (float)(bs & (SS - 1)) * PHI_F;
    float tho = fmaf(ctx, inv, b_out[l * DD + d] + tphi);
    float sv, cv; my_sincos(tho, &sv, &cv);
    float attn = out_scale[l * DD + d] * (cv + sv);
    float r = 0.f;
#pragma unroll
    for (int p = 0; p < 16; ++p) r += g_respart[(p * BS + bs) * DD + d];
    float sil = __fdividef(r, 1.f + __expf(-r));
    float xn = g_x[bs * DD + d] + attn_scale[l] * attn + res_scale[l] * sil;
    if (last) {
        g_xh[bs * DD + d] = __float2half(xn);
    } else {
        g_x[bs * DD + d] = xn;
        g_xT[d * BS + bs] = xn;
    }
}

// ======== K8: logits = x @ Wo^T, fp16 single term, fp32 accum ========
__device__ __forceinline__ void mma16816h(float* c, const unsigned* a, const unsigned* b) {
    asm volatile(
        "mma.sync.aligned.m16n8k16.row.col.f32.f16.f16.f32 "
        "{%0,%1,%2,%3}, {%4,%5,%6,%7}, {%8,%9}, {%0,%1,%2,%3};\n"
        : "+f"(c[0]), "+f"(c[1]), "+f"(c[2]), "+f"(c[3])
        : "r"(a[0]), "r"(a[1]), "r"(a[2]), "r"(a[3]), "r"(b[0]), "r"(b[1]));
}
__device__ __forceinline__ void ldsm4(unsigned& r0, unsigned& r1, unsigned& r2, unsigned& r3,
                                      const void* p) {
    unsigned addr = (unsigned)__cvta_generic_to_shared(p);
    asm volatile("ldmatrix.sync.aligned.m8n8.x4.shared.b16 {%0,%1,%2,%3}, [%4];"
                 : "=r"(r0), "=r"(r1), "=r"(r2), "=r"(r3) : "r"(addr));
}

#define HPITCH 136
#define L_AH 0
#define L_BH (128 * HPITCH * 2)
#define L_SMEM (2 * 128 * HPITCH * 2)       // 69632 B -> 2 CTAs/SM

__global__ __launch_bounds__(256) void logits_fp16_kernel(float* __restrict__ out) {
    extern __shared__ char smem[];
    __half* Ah = reinterpret_cast<__half*>(smem + L_AH);
    __half* Bh = reinterpret_cast<__half*>(smem + L_BH);

    const int n0 = blockIdx.x * 128;
    const int m0 = blockIdx.y * 128;
    const int tid = threadIdx.x;
    const int wid = tid >> 5, lane = tid & 31;
    const int warp_m = wid >> 2;
    const int warp_n = wid & 3;
    const int grp = lane >> 2, t4 = lane & 3;
    const int lrow = lane & 15, lcol8 = (lane >> 4) * 8;

#pragma unroll
    for (int it = 0; it < 8; ++it) {
        int idx = it * 256 + tid;
        int row = idx >> 4, c8 = idx & 15;
        uint4 vh = *reinterpret_cast<const uint4*>(g_xh + (m0 + row) * DD + c8 * 8);
        *reinterpret_cast<uint4*>(Ah + row * HPITCH + c8 * 8) = vh;
    }
#pragma unroll
    for (int it = 0; it < 8; ++it) {
        int idx = it * 256 + tid;
        int row = idx >> 4, c8 = idx & 15;
        int vrow = n0 + row;
        uint4 u = make_uint4(0u, 0u, 0u, 0u);
        if (vrow < VV) u = *reinterpret_cast<const uint4*>(g_Wh + (size_t)vrow * DD + c8 * 8);
        *reinterpret_cast<uint4*>(Bh + row * HPITCH + c8 * 8) = u;
    }
    __syncthreads();

    float acc[4][4][4];
#pragma unroll
    for (int mi = 0; mi < 4; ++mi)
#pragma unroll
        for (int ni = 0; ni < 4; ++ni)
#pragma unroll
            for (int j = 0; j < 4; ++j) acc[mi][ni][j] = 0.f;

#pragma unroll
    for (int kk = 0; kk < DD; kk += 16) {
        unsigned ah[4][4];
#pragma unroll
        for (int mi = 0; mi < 4; ++mi) {
            int r0 = warp_m * 64 + mi * 16 + lrow;
            ldsm4(ah[mi][0], ah[mi][1], ah[mi][2], ah[mi][3], Ah + r0 * HPITCH + kk + lcol8);
        }
        unsigned bh[4][2];
#pragma unroll
        for (int nj = 0; nj < 2; ++nj) {
            int nr = warp_n * 32 + nj * 16 + lrow;
            unsigned r0, r1, r2, r3;
            ldsm4(r0, r1, r2, r3, Bh + nr * HPITCH + kk + lcol8);
            bh[2 * nj][0] = r0; bh[2 * nj][1] = r2;
            bh[2 * nj + 1][0] = r1; bh[2 * nj + 1][1] = r3;
        }
#pragma unroll
        for (int ni = 0; ni < 4; ++ni)
#pragma unroll
            for (int mi = 0; mi < 4; ++mi)
                mma16816h(acc[mi][ni], ah[mi], bh[ni]);
    }

#pragma unroll
    for (int mi = 0; mi < 4; ++mi) {
        int m = m0 + warp_m * 64 + mi * 16 + grp;
        float* row0 = out + (size_t)m * VV;
        float* row1 = out + (size_t)(m + 8) * VV;
#pragma unroll
        for (int ni = 0; ni < 4; ++ni) {
            int n = n0 + warp_n * 32 + ni * 8 + t4 * 2;
            if (n < VV)     row0[n]     = acc[mi][ni][0];
            if (n + 1 < VV) row0[n + 1] = acc[mi][ni][1];
            if (n < VV)     row1[n]     = acc[mi][ni][2];
            if (n + 1 < VV) row1[n + 1] = acc[mi][ni][3];
        }
    }
}

// ---------------- launch: fork attention (stream 0) || ffn (s2), join at update ----
extern "C" void kernel_launch(void* const* d_in, const int* in_sizes, int n_in,
                              void* d_out, int out_size) {
    const int*   tokens     = (const int*)d_in[0];
    const float* emb        = (const float*)d_in[1];
    const float* wq         = (const float*)d_in[2];
    const float* bq         = (const float*)d_in[3];
    const float* wk         = (const float*)d_in[4];
    const float* bk         = (const float*)d_in[5];
    const float* w_out      = (const float*)d_in[6];
    const float* b_out      = (const float*)d_in[7];
    const float* out_scale  = (const float*)d_in[8];
    const float* Wf         = (const float*)d_in[9];
    const float* Bf         = (const float*)d_in[10];
    const float* Pr         = (const float*)d_in[11];
    const float* Pi         = (const float*)d_in[12];
    const float* attn_scale = (const float*)d_in[13];
    const float* res_scale  = (const float*)d_in[14];
    const float* Wo         = (const float*)d_in[15];
    float* out = (float*)d_out;

    static cudaStream_t s2 = nullptr;
    static cudaEvent_t evTop, evFork[LL], evJoin[LL];
    if (!s2) {
        cudaFuncSetAttribute(logits_fp16_kernel,
                             cudaFuncAttributeMaxDynamicSharedMemorySize, L_SMEM);
        cudaStreamCreateWithFlags(&s2, cudaStreamNonBlocking);
        cudaEventCreateWithFlags(&evTop, cudaEventDisableTiming);
        for (int i = 0; i < LL; ++i) {
            cudaEventCreateWithFlags(&evFork[i], cudaEventDisableTiming);
            cudaEventCreateWithFlags(&evJoin[i], cudaEventDisableTiming);
        }
    }

    cudaEventRecord(evTop, 0);
    cudaStreamWaitEvent(s2, evTop, 0);
    cvt_w_kernel<<<((VV * DD / 4) + 255) / 256, 256, 0, s2>>>(Wo);

    scan_kernel<<<BB, DD>>>(tokens, emb);

    for (int l = 0; l < LL; ++l) {
        cudaEventRecord(evFork[l], 0);
        cudaStreamWaitEvent(s2, evFork[l], 0);

        qk_kernel<<<BS, DD>>>(wq, bq, wk, bk, l);
        scores_kernel<<<dim3(SS, BB), 256>>>();

        ffn_kernel<<<dim3(NN / 2, 2), 256, 0, s2>>>(Wf, Bf, l);
        proj_kernel<<<dim3(8, 16), 256, 0, s2>>>(Pr, Pi, l);
        cudaEventRecord(evJoin[l], s2);
        cudaStreamWaitEvent(0, evJoin[l], 0);

        update_kernel<<<BS, DD>>>(w_out, b_out, out_scale, attn_scale, res_scale, l, l == LL - 1);
    }

    logits_fp16_kernel<<<dim3((VV + 127) / 128, 4), 256, L_SMEM>>>(out);
}

// round 14
// speedup vs baseline: 1.0874x; 1.0874x over previous
#include <cuda_runtime.h>
#include <cuda_fp16.h>
#include <math.h>
#include <stdint.h>

#define BB 2
#define SS 256
#define DD 128
#define LL 2
#define NN 512
#define HH 8
#define DHH 16
#define VV 50257
#define BS 512
#define TWO_D 256
#define PHI_F 1.6180339887498949f
#define QT 2

// ---------------- scratch (device globals; no allocations allowed) ----------------
__device__ float g_states[BS * DD];
__device__ float g_x[BS * DD];
__device__ float g_xT[DD * BS];
__device__ float g_q[BS * HH * 32];
__device__ float g_kT[BB * HH * 32 * SS];
__device__ float g_csumT2[2][NN * BS];   // d-split partials (z = d half)
__device__ float g_ssumT2[2][NN * BS];
__device__ float g_context[BS * DD];
__device__ float g_respart[16 * BS * DD];
// fp16 operands for the tensor-core logits GEMM
__device__ __align__(16) __half g_xh[BS * DD];
__device__ __align__(16) __half g_Wh[VV * DD];

// Accurate sincos regardless of fast-math flags: Cody-Waite reduce to
// [-pi,pi], then fast-path __sincosf (error ~2^-21 there).
__device__ __forceinline__ void my_sincos(float th, float* sp, float* cp) {
    float k = rintf(th * 0.15915494309189535f);
    float r = fmaf(k, -6.28125f, th);
    r = fmaf(k, -1.9353071795864769e-3f, r);
    __sincosf(r, sp, cp);
}

// ---------------- K0: Wo fp32 -> fp16 (once per call; overlapped on stream 2) ------
__global__ void cvt_w_kernel(const float* __restrict__ Wo) {
    int i = blockIdx.x * 256 + threadIdx.x;   // over VV*DD/4
    if (i >= (VV * DD) / 4) return;
    float4 v = reinterpret_cast<const float4*>(Wo)[i];
    __half2 p0 = __floats2half2_rn(v.x, v.y);
    __half2 p1 = __floats2half2_rn(v.z, v.w);
    uint2 u = make_uint2(*reinterpret_cast<unsigned*>(&p0), *reinterpret_cast<unsigned*>(&p1));
    reinterpret_cast<uint2*>(g_Wh)[i] = u;
}

// ---------------- K1: embedding + sequential scan, chunked register prefetch -------
#define CH 16
__global__ void scan_kernel(const int* __restrict__ tokens, const float* __restrict__ emb) {
    int b = blockIdx.x, d = threadIdx.x;
    const int* tk = tokens + b * SS;
    float w_r[CH], be_r[CH];

#pragma unroll
    for (int i = 0; i < CH; ++i) {
        int tok = __ldg(&tk[i]);
        w_r[i]  = __ldg(&emb[tok * TWO_D + d]);
        be_r[i] = __ldg(&emb[tok * TWO_D + DD + d]);
    }

    float s = 0.f;
    for (int c = 0; c < SS / CH; ++c) {
        float inv_c[CH], base_c[CH];
#pragma unroll
        for (int i = 0; i < CH; ++i) {
            inv_c[i]  = __fdividef(1.f, 1.f + fabsf(w_r[i]));
            base_c[i] = fmaf((float)(c * CH + i), PHI_F, be_r[i]);
        }
        if (c + 1 < SS / CH) {
#pragma unroll
            for (int i = 0; i < CH; ++i) {
                int tok = __ldg(&tk[(c + 1) * CH + i]);
                w_r[i]  = __ldg(&emb[tok * TWO_D + d]);
                be_r[i] = __ldg(&emb[tok * TWO_D + DD + d]);
            }
        }
#pragma unroll
        for (int i = 0; i < CH; ++i) {
            float th = fmaf(s, inv_c[i], base_c[i]);
            float sv, cv; my_sincos(th, &sv, &cv);
            s = cv + sv;
            int bs = b * SS + c * CH + i;
            g_states[bs * DD + d] = s;
            g_x[bs * DD + d] = s;
            g_xT[d * BS + bs] = s;
        }
    }
}

// ---------------- K2: build q and transposed k ----------------
__global__ void qk_kernel(const float* __restrict__ wq, const float* __restrict__ bq,
                          const float* __restrict__ wk, const float* __restrict__ bk, int l) {
    int bs = blockIdx.x, d = threadIdx.x;
    int h = d >> 4, dh = d & 15;
    int t = bs & (SS - 1);
    float tphi = (float)t * PHI_F;
    int wi = (l * HH + h) * DHH + dh;

    float xv = g_x[bs * DD + d];
    float iq = __fdividef(1.f, 1.f + fabsf(wq[wi]));
    float thq = fmaf(xv, iq, bq[wi] + tphi);
    float sq, cq; my_sincos(thq, &sq, &cq);
    int qb = bs * (HH * 32) + h * 32;
    g_q[qb + dh] = cq;
    g_q[qb + 16 + dh] = sq;

    float sv = g_states[bs * DD + d];
    float ik = __fdividef(1.f, 1.f + fabsf(wk[wi]));
    float thk = fmaf(sv, ik, bk[wi]);
    float sk, ck; my_sincos(thk, &sk, &ck);
    int b = bs >> 8, si = bs & 255;
    int kb = (b * HH + h) * 32;
    g_kT[(kb + dh) * SS + si] = ck;
    g_kT[(kb + 16 + dh) * SS + si] = sk;
}

// ---------------- K3: scores + softmax + head-sum + context, Q-tiled x2 (R11) ------
__global__ __launch_bounds__(256) void scores_kernel() {
    int q0 = blockIdx.x * QT, b = blockIdx.y;
    int tid = threadIdx.x;
    int h = tid >> 5, lane = tid & 31;
    __shared__ float q_sh[QT][HH * 32];
    __shared__ float wts_sh[HH][QT][SS];
    __shared__ float wsum_sh[QT][SS];

#pragma unroll
    for (int i = 0; i < QT; ++i)
        q_sh[i][tid] = g_q[(b * SS + q0 + i) * (HH * 32) + tid];
    __syncthreads();

    const float* kbase = g_kT + (b * HH + h) * 32 * SS;
    float acc[QT][8];
#pragma unroll
    for (int qi = 0; qi < QT; ++qi)
#pragma unroll
        for (int j = 0; j < 8; ++j) acc[qi][j] = 0.f;

#pragma unroll 4
    for (int dd = 0; dd < 32; ++dd) {
        const float4* row = reinterpret_cast<const float4*>(kbase + dd * SS);
        float4 v0 = row[lane];
        float4 v1 = row[lane + 32];
#pragma unroll
        for (int qi = 0; qi < QT; ++qi) {
            float qv = q_sh[qi][h * 32 + dd];
            acc[qi][0] = fmaf(qv, v0.x, acc[qi][0]); acc[qi][1] = fmaf(qv, v0.y, acc[qi][1]);
            acc[qi][2] = fmaf(qv, v0.z, acc[qi][2]); acc[qi][3] = fmaf(qv, v0.w, acc[qi][3]);
            acc[qi][4] = fmaf(qv, v1.x, acc[qi][4]); acc[qi][5] = fmaf(qv, v1.y, acc[qi][5]);
            acc[qi][6] = fmaf(qv, v1.z, acc[qi][6]); acc[qi][7] = fmaf(qv, v1.w, acc[qi][7]);
        }
    }

    const float iscale = 0.17677669529663687f;  // 1/sqrt(32)
    int k0 = 4 * lane;
#pragma unroll
    for (int qi = 0; qi < QT; ++qi) {
        int q = q0 + qi;
        float m = -1e30f;
#pragma unroll
        for (int j = 0; j < 8; ++j) {
            acc[qi][j] *= iscale;
            int ki = (j < 4) ? (k0 + j) : (128 + k0 + j - 4);
            if (ki <= q && acc[qi][j] > m) m = acc[qi][j];
        }
#pragma unroll
        for (int o = 16; o; o >>= 1) m = fmaxf(m, __shfl_xor_sync(0xffffffffu, m, o));
        float e[8]; float sum = 0.f;
#pragma unroll
        for (int j = 0; j < 8; ++j) {
            int ki = (j < 4) ? (k0 + j) : (128 + k0 + j - 4);
            e[j] = (ki <= q) ? __expf(acc[qi][j] - m) : 0.f;
            sum += e[j];
        }
#pragma unroll
        for (int o = 16; o; o >>= 1) sum += __shfl_xor_sync(0xffffffffu, sum, o);
        float inv = __fdividef(1.f, sum);
        float4 w0 = make_float4(e[0] * inv, e[1] * inv, e[2] * inv, e[3] * inv);
        float4 w1 = make_float4(e[4] * inv, e[5] * inv, e[6] * inv, e[7] * inv);
        reinterpret_cast<float4*>(&wts_sh[h][qi][0])[lane] = w0;
        reinterpret_cast<float4*>(&wts_sh[h][qi][0])[lane + 32] = w1;
    }
    __syncthreads();

#pragma unroll
    for (int i = 0; i < QT; ++i) {
        int idx = i * 256 + tid;
        int qi = idx >> 8, k = idx & 255;
        float ws = 0.f;
#pragma unroll
        for (int hh = 0; hh < HH; ++hh) ws += wts_sh[hh][qi][k];
        wsum_sh[qi][k] = ws;
    }
    __syncthreads();

    int d = tid & 127, half = tid >> 7;
    float cacc[QT];
#pragma unroll
    for (int qi = 0; qi < QT; ++qi) cacc[qi] = 0.f;
    const float* st = g_states + b * SS * DD + d;
    int kbeg = half << 7;
#pragma unroll 4
    for (int k = kbeg; k < kbeg + 128; ++k) {
        float sv = st[k * DD];
#pragma unroll
        for (int qi = 0; qi < QT; ++qi) cacc[qi] = fmaf(wsum_sh[qi][k], sv, cacc[qi]);
    }
    float* red = &wts_sh[0][0][0];
    if (half == 1) {
#pragma unroll
        for (int qi = 0; qi < QT; ++qi) red[qi * 128 + d] = cacc[qi];
    }
    __syncthreads();
    if (half == 0) {
#pragma unroll
        for (int qi = 0; qi < QT; ++qi)
            g_context[(b * SS + q0 + qi) * DD + d] = cacc[qi] + red[qi * 128 + d];
    }
}

// ---------------- K6: FFN random-feature sums, d-split x2 (critical path) ----------
// grid (NN/2, 2, 2): blockIdx.z selects d half; rotation is linear so halves
// rotate independently and proj adds the partials.
__global__ __launch_bounds__(256) void ffn_kernel(const float* __restrict__ Wf,
                                                  const float* __restrict__ Bf, int l) {
    int n0 = blockIdx.x * 2, tid = threadIdx.x;
    int bs = blockIdx.y * 256 + tid;
    int z = blockIdx.z, d0 = z * 64;
    __shared__ float inv_sh[2][64], c_sh[2][64];
    if (tid < 128) {
        int np = tid >> 6, d = tid & 63;
        inv_sh[np][d] = __fdividef(1.f, 1.f + fabsf(Wf[(l * NN + n0 + np) * DD + d0 + d]));
        c_sh[np][d] = Bf[(l * NN + n0 + np) * DD + d0 + d];
    }
    __syncthreads();

    float ac[2] = {0.f, 0.f}, as2[2] = {0.f, 0.f};
#pragma unroll 4
    for (int dd = 0; dd < 64; ++dd) {
        float xv = g_xT[(d0 + dd) * BS + bs];
        float su, cu;
        __sincosf(fmaf(xv, inv_sh[0][dd], c_sh[0][dd]), &su, &cu);
        ac[0] += cu; as2[0] += su;
        __sincosf(fmaf(xv, inv_sh[1][dd], c_sh[1][dd]), &su, &cu);
        ac[1] += cu; as2[1] += su;
    }
    float st0, ct0;
    my_sincos((float)(bs & (SS - 1)), &st0, &ct0);
#pragma unroll
    for (int np = 0; np < 2; ++np) {
        int n = n0 + np;
        g_csumT2[z][n * BS + bs] = ct0 * ac[np] - st0 * as2[np];
        g_ssumT2[z][n * BS + bs] = st0 * ac[np] + ct0 * as2[np];
    }
}

// ---------------- K7a: res partial GEMM (k-split x16; A = sum of d-halves) --------
__global__ __launch_bounds__(256) void proj_kernel(const float* __restrict__ Pr,
                                                   const float* __restrict__ Pi, int l) {
    int m0 = blockIdx.x * 64;
    int p = blockIdx.y;
    int k0 = p * 32;
    int tid = threadIdx.x;
    int tx = tid & 15, ty = tid >> 4;
    __shared__ float Ac[16][64], As2[16][64], Br[16][128], Bi[16][128];
    float acc[4][8];
#pragma unroll
    for (int i = 0; i < 4; ++i)
#pragma unroll
        for (int j = 0; j < 8; ++j) acc[i][j] = 0.f;

    for (int kc = 0; kc < 2; ++kc) {
        int kb = k0 + kc * 16;
        {
            int r = tid >> 4, c4 = tid & 15;
            int off = (kb + r) * BS + m0 + c4 * 4;
            float4 v0 = *reinterpret_cast<const float4*>(&g_csumT2[0][off]);
            float4 v1 = *reinterpret_cast<const float4*>(&g_csumT2[1][off]);
            Ac[r][c4 * 4 + 0] = v0.x + v1.x; Ac[r][c4 * 4 + 1] = v0.y + v1.y;
            Ac[r][c4 * 4 + 2] = v0.z + v1.z; Ac[r][c4 * 4 + 3] = v0.w + v1.w;
            float4 s0 = *reinterpret_cast<const float4*>(&g_ssumT2[0][off]);
            float4 s1 = *reinterpret_cast<const float4*>(&g_ssumT2[1][off]);
            As2[r][c4 * 4 + 0] = s0.x + s1.x; As2[r][c4 * 4 + 1] = s0.y + s1.y;
            As2[r][c4 * 4 + 2] = s0.z + s1.z; As2[r][c4 * 4 + 3] = s0.w + s1.w;
        }
#pragma unroll
        for (int i = 0; i < 2; ++i) {
            int idx = tid * 2 + i;
            int dcol = idx >> 2, k4 = idx & 3;
            float4 v = *reinterpret_cast<const float4*>(Pr + (l * DD + dcol) * NN + kb + k4 * 4);
            Br[k4 * 4 + 0][dcol] = v.x; Br[k4 * 4 + 1][dcol] = v.y;
            Br[k4 * 4 + 2][dcol] = v.z; Br[k4 * 4 + 3][dcol] = v.w;
            float4 v2 = *reinterpret_cast<const float4*>(Pi + (l * DD + dcol) * NN + kb + k4 * 4);
            Bi[k4 * 4 + 0][dcol] = v2.x; Bi[k4 * 4 + 1][dcol] = v2.y;
            Bi[k4 * 4 + 2][dcol] = v2.z; Bi[k4 * 4 + 3][dcol] = v2.w;
        }
        __syncthreads();
#pragma unroll
        for (int kk = 0; kk < 16; ++kk) {
            float a_c[4], a_s[4], b_r[8], b_i[8];
#pragma unroll
            for (int i = 0; i < 4; ++i) { a_c[i] = Ac[kk][ty * 4 + i]; a_s[i] = As2[kk][ty * 4 + i]; }
#pragma unroll
            for (int j = 0; j < 8; ++j) { b_r[j] = Br[kk][tx * 8 + j]; b_i[j] = Bi[kk][tx * 8 + j]; }
#pragma unroll
            for (int i = 0; i < 4; ++i)
#pragma unroll
                for (int j = 0; j < 8; ++j)
                    acc[i][j] = fmaf(a_s[i], b_i[j], fmaf(a_c[i], b_r[j], acc[i][j]));
        }
        __syncthreads();
    }
#pragma unroll
    for (int i = 0; i < 4; ++i)
#pragma unroll
        for (int j = 0; j < 8; ++j)
            g_respart[(p * BS + m0 + ty * 4 + i) * DD + tx * 8 + j] = acc[i][j];
}

// ---------------- K7b: attn_out + silu(res) + x update (+fp16 on last layer) --------
__global__ void update_kernel(const float* __restrict__ w_out, const float* __restrict__ b_out,
                              const float* __restrict__ out_scale, const float* __restrict__ attn_scale,
                              const float* __restrict__ res_scale, int l, int last) {
    int bs = blockIdx.x, d = threadIdx.x;
    float ctx = g_context[bs * DD + d];
    float inv = __fdividef(1.f, 1.f + fabsf(w_out[l * DD + d]));
    float tphi = (float)(bs & (SS - 1)) * PHI_F;
    float tho = fmaf(ctx, inv, b_out[l * DD + d] + tphi);
    float sv, cv; my_sincos(tho, &sv, &cv);
    float attn = out_scale[l * DD + d] * (cv + sv);
    float r = 0.f;
#pragma unroll
    for (int p = 0; p < 16; ++p) r += g_respart[(p * BS + bs) * DD + d];
    float sil = __fdividef(r, 1.f + __expf(-r));
    float xn = g_x[bs * DD + d] + attn_scale[l] * attn + res_scale[l] * sil;
    if (last) {
        g_xh[bs * DD + d] = __float2half(xn);
    } else {
        g_x[bs * DD + d] = xn;
        g_xT[d * BS + bs] = xn;
    }
}

// ======== K8: logits = x @ Wo^T, fp16 single term, fp32 accum ========
__device__ __forceinline__ void mma16816h(float* c, const unsigned* a, const unsigned* b) {
    asm volatile(
        "mma.sync.aligned.m16n8k16.row.col.f32.f16.f16.f32 "
        "{%0,%1,%2,%3}, {%4,%5,%6,%7}, {%8,%9}, {%0,%1,%2,%3};\n"
        : "+f"(c[0]), "+f"(c[1]), "+f"(c[2]), "+f"(c[3])
        : "r"(a[0]), "r"(a[1]), "r"(a[2]), "r"(a[3]), "r"(b[0]), "r"(b[1]));
}
__device__ __forceinline__ void ldsm4(unsigned& r0, unsigned& r1, unsigned& r2, unsigned& r3,
                                      const void* p) {
    unsigned addr = (unsigned)__cvta_generic_to_shared(p);
    asm volatile("ldmatrix.sync.aligned.m8n8.x4.shared.b16 {%0,%1,%2,%3}, [%4];"
                 : "=r"(r0), "=r"(r1), "=r"(r2), "=r"(r3) : "r"(addr));
}

#define HPITCH 136
#define L_AH 0
#define L_BH (128 * HPITCH * 2)
#define L_SMEM (2 * 128 * HPITCH * 2)       // 69632 B -> 2 CTAs/SM

__global__ __launch_bounds__(256) void logits_fp16_kernel(float* __restrict__ out) {
    extern __shared__ char smem[];
    __half* Ah = reinterpret_cast<__half*>(smem + L_AH);
    __half* Bh = reinterpret_cast<__half*>(smem + L_BH);

    const int n0 = blockIdx.x * 128;
    const int m0 = blockIdx.y * 128;
    const int tid = threadIdx.x;
    const int wid = tid >> 5, lane = tid & 31;
    const int warp_m = wid >> 2;
    const int warp_n = wid & 3;
    const int grp = lane >> 2, t4 = lane & 3;
    const int lrow = lane & 15, lcol8 = (lane >> 4) * 8;

#pragma unroll
    for (int it = 0; it < 8; ++it) {
        int idx = it * 256 + tid;
        int row = idx >> 4, c8 = idx & 15;
        uint4 vh = *reinterpret_cast<const uint4*>(g_xh + (m0 + row) * DD + c8 * 8);
        *reinterpret_cast<uint4*>(Ah + row * HPITCH + c8 * 8) = vh;
    }
#pragma unroll
    for (int it = 0; it < 8; ++it) {
        int idx = it * 256 + tid;
        int row = idx >> 4, c8 = idx & 15;
        int vrow = n0 + row;
        uint4 u = make_uint4(0u, 0u, 0u, 0u);
        if (vrow < VV) u = *reinterpret_cast<const uint4*>(g_Wh + (size_t)vrow * DD + c8 * 8);
        *reinterpret_cast<uint4*>(Bh + row * HPITCH + c8 * 8) = u;
    }
    __syncthreads();

    float acc[4][4][4];
#pragma unroll
    for (int mi = 0; mi < 4; ++mi)
#pragma unroll
        for (int ni = 0; ni < 4; ++ni)
#pragma unroll
            for (int j = 0; j < 4; ++j) acc[mi][ni][j] = 0.f;

#pragma unroll
    for (int kk = 0; kk < DD; kk += 16) {
        unsigned ah[4][4];
#pragma unroll
        for (int mi = 0; mi < 4; ++mi) {
            int r0 = warp_m * 64 + mi * 16 + lrow;
            ldsm4(ah[mi][0], ah[mi][1], ah[mi][2], ah[mi][3], Ah + r0 * HPITCH + kk + lcol8);
        }
        unsigned bh[4][2];
#pragma unroll
        for (int nj = 0; nj < 2; ++nj) {
            int nr = warp_n * 32 + nj * 16 + lrow;
            unsigned r0, r1, r2, r3;
            ldsm4(r0, r1, r2, r3, Bh + nr * HPITCH + kk + lcol8);
            bh[2 * nj][0] = r0; bh[2 * nj][1] = r2;
            bh[2 * nj + 1][0] = r1; bh[2 * nj + 1][1] = r3;
        }
#pragma unroll
        for (int ni = 0; ni < 4; ++ni)
#pragma unroll
            for (int mi = 0; mi < 4; ++mi)
                mma16816h(acc[mi][ni], ah[mi], bh[ni]);
    }

#pragma unroll
    for (int mi = 0; mi < 4; ++mi) {
        int m = m0 + warp_m * 64 + mi * 16 + grp;
        float* row0 = out + (size_t)m * VV;
        float* row1 = out + (size_t)(m + 8) * VV;
#pragma unroll
        for (int ni = 0; ni < 4; ++ni) {
            int n = n0 + warp_n * 32 + ni * 8 + t4 * 2;
            if (n < VV)     row0[n]     = acc[mi][ni][0];
            if (n + 1 < VV) row0[n + 1] = acc[mi][ni][1];
            if (n < VV)     row1[n]     = acc[mi][ni][2];
            if (n + 1 < VV) row1[n + 1] = acc[mi][ni][3];
        }
    }
}

// ---------------- launch: fork attention (stream 0) || ffn (s2), join at update ----
extern "C" void kernel_launch(void* const* d_in, const int* in_sizes, int n_in,
                              void* d_out, int out_size) {
    const int*   tokens     = (const int*)d_in[0];
    const float* emb        = (const float*)d_in[1];
    const float* wq         = (const float*)d_in[2];
    const float* bq         = (const float*)d_in[3];
    const float* wk         = (const float*)d_in[4];
    const float* bk         = (const float*)d_in[5];
    const float* w_out      = (const float*)d_in[6];
    const float* b_out      = (const float*)d_in[7];
    const float* out_scale  = (const float*)d_in[8];
    const float* Wf         = (const float*)d_in[9];
    const float* Bf         = (const float*)d_in[10];
    const float* Pr         = (const float*)d_in[11];
    const float* Pi         = (const float*)d_in[12];
    const float* attn_scale = (const float*)d_in[13];
    const float* res_scale  = (const float*)d_in[14];
    const float* Wo         = (const float*)d_in[15];
    float* out = (float*)d_out;

    static cudaStream_t s2 = nullptr;
    static cudaEvent_t evTop, evFork[LL], evJoin[LL];
    if (!s2) {
        cudaFuncSetAttribute(logits_fp16_kernel,
                             cudaFuncAttributeMaxDynamicSharedMemorySize, L_SMEM);
        cudaStreamCreateWithFlags(&s2, cudaStreamNonBlocking);
        cudaEventCreateWithFlags(&evTop, cudaEventDisableTiming);
        for (int i = 0; i < LL; ++i) {
            cudaEventCreateWithFlags(&evFork[i], cudaEventDisableTiming);
            cudaEventCreateWithFlags(&evJoin[i], cudaEventDisableTiming);
        }
    }

    cudaEventRecord(evTop, 0);
    cudaStreamWaitEvent(s2, evTop, 0);
    cvt_w_kernel<<<((VV * DD / 4) + 255) / 256, 256, 0, s2>>>(Wo);

    scan_kernel<<<BB, DD>>>(tokens, emb);

    for (int l = 0; l < LL; ++l) {
        cudaEventRecord(evFork[l], 0);
        cudaStreamWaitEvent(s2, evFork[l], 0);

        qk_kernel<<<BS, DD>>>(wq, bq, wk, bk, l);
        scores_kernel<<<dim3(SS / QT, BB), 256>>>();

        ffn_kernel<<<dim3(NN / 2, 2, 2), 256, 0, s2>>>(Wf, Bf, l);
        proj_kernel<<<dim3(8, 16), 256, 0, s2>>>(Pr, Pi, l);
        cudaEventRecord(evJoin[l], s2);
        cudaStreamWaitEvent(0, evJoin[l], 0);

        update_kernel<<<BS, DD>>>(w_out, b_out, out_scale, attn_scale, res_scale, l, l == LL - 1);
    }

    logits_fp16_kernel<<<dim3((VV + 127) / 128, 4), 256, L_SMEM>>>(out);
}